// round 13
// baseline (speedup 1.0000x reference)
#include <cuda_runtime.h>
#include <cuda_bf16.h>
#include <mma.h>
#include <cstdint>

using namespace nvcuda;
typedef __nv_bfloat16 bf16;

#define BATCH 4
#define CCH   256
#define GRP   32
#define NTOK  4096
#define EPS   1e-6f
// exp(q.k/16) = 2^(q'.k) with q' = q * log2(e)/16
#define QSCALE 0.09016843785f

// ---------------------------- PTX helpers -----------------------------------
__device__ __forceinline__ uint32_t smem_to_u32(const void* p) {
    uint32_t a;
    asm("{ .reg .u64 tmp; cvta.to.shared.u64 tmp, %1; cvt.u32.u64 %0, tmp; }"
        : "=r"(a) : "l"(p));
    return a;
}
#define CP_ASYNC16(dst, src) \
    asm volatile("cp.async.cg.shared.global [%0], [%1], 16;" :: "r"(dst), "l"(src))
#define CP_COMMIT() asm volatile("cp.async.commit_group;" ::: "memory")
#define CP_WAIT(n)  asm volatile("cp.async.wait_group %0;" :: "n"(n) : "memory")

__device__ __forceinline__ void ldsm_x4(uint32_t addr, uint32_t r[4]) {
    asm volatile("ldmatrix.sync.aligned.m8n8.x4.shared.b16 {%0,%1,%2,%3}, [%4];"
                 : "=r"(r[0]), "=r"(r[1]), "=r"(r[2]), "=r"(r[3]) : "r"(addr));
}
__device__ __forceinline__ void ldsm_x4t(uint32_t addr, uint32_t r[4]) {
    asm volatile("ldmatrix.sync.aligned.m8n8.x4.trans.shared.b16 {%0,%1,%2,%3}, [%4];"
                 : "=r"(r[0]), "=r"(r[1]), "=r"(r[2]), "=r"(r[3]) : "r"(addr));
}
// bf16 MMA: D(f32) += A(bf16 m16k16) * B(bf16 k16n8)
__device__ __forceinline__ void mma16816(float c[4], const uint32_t a[4],
                                         uint32_t b0, uint32_t b1) {
    asm volatile("mma.sync.aligned.m16n8k16.row.col.f32.bf16.bf16.f32 "
                 "{%0,%1,%2,%3}, {%4,%5,%6,%7}, {%8,%9}, {%0,%1,%2,%3};"
                 : "+f"(c[0]), "+f"(c[1]), "+f"(c[2]), "+f"(c[3])
                 : "r"(a[0]), "r"(a[1]), "r"(a[2]), "r"(a[3]), "r"(b0), "r"(b1));
}
// fp8 e4m3 MMA: D(f32) += A(e4m3 m16k32) * B(e4m3 k32n8)
__device__ __forceinline__ void mma16832(float c[4], const uint32_t a[4],
                                         uint32_t b0, uint32_t b1) {
    asm volatile("mma.sync.aligned.m16n8k32.row.col.f32.e4m3.e4m3.f32 "
                 "{%0,%1,%2,%3}, {%4,%5,%6,%7}, {%8,%9}, {%0,%1,%2,%3};"
                 : "+f"(c[0]), "+f"(c[1]), "+f"(c[2]), "+f"(c[3])
                 : "r"(a[0]), "r"(a[1]), "r"(a[2]), "r"(a[3]), "r"(b0), "r"(b1));
}
__device__ __forceinline__ float ex2f(float x) {
    float y;
    asm("ex2.approx.f32 %0, %1;" : "=f"(y) : "f"(x));
    return y;
}
__device__ __forceinline__ uint32_t packbf2(float a, float b) {
    __nv_bfloat162 h = __floats2bfloat162_rn(a, b);
    return *(uint32_t*)&h;
}
__device__ __forceinline__ uint32_t pack_e4m3(float lo, float hi) {
    uint16_t r;
    asm("cvt.rn.satfinite.e4m3x2.f32 %0, %1, %2;" : "=h"(r) : "f"(hi), "f"(lo));
    return (uint32_t)r;
}
__device__ __forceinline__ void sts32(uint32_t addr, uint32_t v) {
    asm volatile("st.shared.b32 [%0], %1;" :: "r"(addr), "r"(v));
}

// ---------------- scratch (device globals; no allocs allowed) ----------------
__device__ float   g_mean[BATCH * GRP];
__device__ float   g_rstd[BATCH * GRP];
__device__ bf16    g_hn[BATCH * NTOK * CCH];   // [b][n][c]
__device__ bf16    g_wb[4][CCH * CCH];         // wq,wk,wv,wp in bf16
__device__ uint8_t g_q8[BATCH * NTOK * CCH];   // [b][n][c]  e4m3, pre-scaled
__device__ uint8_t g_k8[BATCH * NTOK * CCH];   // [b][n][c]  e4m3
__device__ bf16    g_v [BATCH * NTOK * CCH];   // [b][n][c]  bf16
__device__ bf16    g_a [BATCH * NTOK * CCH];   // attention output (normalized)

// ---------------- 0) weight conversion fp32 -> bf16 ----------------
__global__ void w_cvt(const float* __restrict__ wq, const float* __restrict__ wk,
                      const float* __restrict__ wv, const float* __restrict__ wp) {
    int i = blockIdx.x * blockDim.x + threadIdx.x;   // 0..16383 (float4 index)
    const float* srcs[4] = {wq, wk, wv, wp};
    #pragma unroll
    for (int m = 0; m < 4; m++) {
        float4 f = ((const float4*)srcs[m])[i];
        __nv_bfloat162* d = (__nv_bfloat162*)&g_wb[m][i * 4];
        d[0] = __float22bfloat162_rn(make_float2(f.x, f.y));
        d[1] = __float22bfloat162_rn(make_float2(f.z, f.w));
    }
}

// ---------------- 1) GroupNorm statistics ----------------
__global__ void gn_stats(const float* __restrict__ x) {
    int bg = blockIdx.x;
    const float4* p = (const float4*)(x + (size_t)bg * (8 * NTOK));
    float s = 0.f, sq = 0.f;
    for (int i = threadIdx.x; i < (8 * NTOK) / 4; i += blockDim.x) {
        float4 v = p[i];
        s  += v.x + v.y + v.z + v.w;
        sq += v.x * v.x + v.y * v.y + v.z * v.z + v.w * v.w;
    }
    __shared__ float ss[32], ssq[32];
    #pragma unroll
    for (int o = 16; o; o >>= 1) {
        s  += __shfl_xor_sync(~0u, s, o);
        sq += __shfl_xor_sync(~0u, sq, o);
    }
    int w = threadIdx.x >> 5, l = threadIdx.x & 31;
    if (l == 0) { ss[w] = s; ssq[w] = sq; }
    __syncthreads();
    if (w == 0) {
        s  = (l < (int)(blockDim.x >> 5)) ? ss[l]  : 0.f;
        sq = (l < (int)(blockDim.x >> 5)) ? ssq[l] : 0.f;
        #pragma unroll
        for (int o = 16; o; o >>= 1) {
            s  += __shfl_xor_sync(~0u, s, o);
            sq += __shfl_xor_sync(~0u, sq, o);
        }
        if (l == 0) {
            float m   = s / (8.f * NTOK);
            float var = sq / (8.f * NTOK) - m * m;
            g_mean[bg] = m;
            g_rstd[bg] = rsqrtf(var + EPS);
        }
    }
}

// ------- 2) GroupNorm apply + transpose to bf16 [b][n][c] -------
__global__ void gn_apply(const float* __restrict__ x,
                         const float* __restrict__ gs,
                         const float* __restrict__ gb) {
    __shared__ float tile[32][33];
    int n0 = blockIdx.x * 32, c0 = blockIdx.y * 32, b = blockIdx.z;
    int tx = threadIdx.x, ty = threadIdx.y;
    #pragma unroll
    for (int j = 0; j < 4; j++) {
        int c = c0 + ty + j * 8;
        float v = x[((size_t)(b * CCH + c)) * NTOK + n0 + tx];
        int gi = b * GRP + (c >> 3);
        v = (v - g_mean[gi]) * g_rstd[gi] * gs[c] + gb[c];
        tile[ty + j * 8][tx] = v;
    }
    __syncthreads();
    #pragma unroll
    for (int j = 0; j < 4; j++) {
        int n = n0 + ty + j * 8;
        g_hn[((size_t)(b * NTOK + n)) * CCH + c0 + tx] =
            __float2bfloat16(tile[tx][ty + j * 8]);
    }
}

// -------- 3) fused QKV GEMM, cp.async + bf16 weights. z=(b,sel). -------------
#define GT 18432                          // one tile: 128 x 144 B
#define QKV_SMEM (4 * GT)                 // 73728 (>= epilogue 69632)

__device__ __forceinline__ void gemm_tile_load(uint32_t sA, uint32_t sB,
                                               const char* Ab, const char* Bb,
                                               int m0, int d0, int ch, int t) {
    #pragma unroll
    for (int i = 0; i < 4; i++) {
        int s = t + i * 256;
        int r = s >> 3, c = s & 7;
        CP_ASYNC16(sA + r * 144 + c * 16, Ab + (size_t)(m0 + r) * 512 + ch * 128 + c * 16);
    }
    #pragma unroll
    for (int i = 0; i < 4; i++) {
        int s = t + i * 256;
        int r = s >> 3, c = s & 7;
        CP_ASYNC16(sB + r * 144 + c * 16, Bb + (size_t)(d0 + r) * 512 + ch * 128 + c * 16);
    }
}

__global__ void __launch_bounds__(256) qkv_gemm(
        const float* __restrict__ bq, const float* __restrict__ bk,
        const float* __restrict__ bv) {
    extern __shared__ char sm[];
    uint32_t smb = smem_to_u32(sm);
    float* sOut = (float*)sm;

    int m0  = blockIdx.x * 128;
    int d0  = blockIdx.y * 128;
    int b   = blockIdx.z / 3;
    int sel = blockIdx.z % 3;
    const float* bias = (sel == 0) ? bq : (sel == 1) ? bk : bv;
    const char* Ab = (const char*)(g_hn + (size_t)b * NTOK * CCH);
    const char* Bb = (const char*)(g_wb[sel]);

    int t = threadIdx.x;
    int wid = t >> 5;
    int wm = wid & 3, wn = wid >> 2;

    wmma::fragment<wmma::accumulator, 16, 16, 16, float> acc[2][4];
    #pragma unroll
    for (int i = 0; i < 2; i++)
        #pragma unroll
        for (int j = 0; j < 4; j++) wmma::fill_fragment(acc[i][j], 0.f);

    gemm_tile_load(smb, smb + GT, Ab, Bb, m0, d0, 0, t);
    CP_COMMIT();

    for (int ch = 0; ch < 4; ch++) {
        if (ch + 1 < 4) {
            gemm_tile_load(smb + ((ch + 1) & 1) * 2 * GT,
                           smb + ((ch + 1) & 1) * 2 * GT + GT, Ab, Bb, m0, d0, ch + 1, t);
            CP_COMMIT();
            CP_WAIT(1);
        } else {
            CP_WAIT(0);
        }
        __syncthreads();
        bf16* sA = (bf16*)(sm + (ch & 1) * 2 * GT);
        bf16* sB = (bf16*)(sm + (ch & 1) * 2 * GT + GT);
        #pragma unroll
        for (int ks = 0; ks < 4; ks++) {
            wmma::fragment<wmma::matrix_a, 16, 16, 16, bf16, wmma::row_major> af0, af1;
            wmma::load_matrix_sync(af0, &sA[(wm * 32) * 72 + ks * 16], 72);
            wmma::load_matrix_sync(af1, &sA[(wm * 32 + 16) * 72 + ks * 16], 72);
            #pragma unroll
            for (int ni = 0; ni < 4; ni++) {
                wmma::fragment<wmma::matrix_b, 16, 16, 16, bf16, wmma::col_major> bfr;
                wmma::load_matrix_sync(bfr, &sB[ks * 16 + (wn * 64 + ni * 16) * 72], 72);
                wmma::mma_sync(acc[0][ni], af0, bfr, acc[0][ni]);
                wmma::mma_sync(acc[1][ni], af1, bfr, acc[1][ni]);
            }
        }
        __syncthreads();
    }
    #pragma unroll
    for (int i = 0; i < 2; i++)
        #pragma unroll
        for (int j = 0; j < 4; j++)
            wmma::store_matrix_sync(&sOut[(wm * 32 + i * 16) * 136 + wn * 64 + j * 16],
                                    acc[i][j], 136, wmma::mem_row_major);
    __syncthreads();
    if (sel == 2) {
        for (int idx = t; idx < 128 * 128; idx += 256) {
            int r = idx >> 7, cc = idx & 127;
            float v = sOut[r * 136 + cc] + bias[d0 + cc];
            g_v[(size_t)(b * NTOK + m0 + r) * CCH + d0 + cc] = __float2bfloat16(v);
        }
    } else {
        uint8_t* out = (sel == 0) ? g_q8 : g_k8;
        float oscale = (sel == 0) ? QSCALE : 1.0f;
        for (int idx = t; idx < 128 * 64; idx += 256) {
            int r = idx >> 6, cc = idx & 63;
            float v0 = (sOut[r * 136 + 2 * cc]     + bias[d0 + 2 * cc])     * oscale;
            float v1 = (sOut[r * 136 + 2 * cc + 1] + bias[d0 + 2 * cc + 1]) * oscale;
            uint16_t pk = (uint16_t)pack_e4m3(v0, v1);
            *(uint16_t*)(out + (size_t)(b * NTOK + m0 + r) * CCH + d0 + 2 * cc) = pk;
        }
    }
}

// ------------------- 4) Flash attention: Q in registers ---------------------
// BM=128 rows/CTA, 8 warps: grp=w&3 owns rows grp*32..+32, dhalf=w>>2 owns
// channels dhalf*128..+128 (and tokens dhalf*32..+32 for S). BN=64.
// Q fp8 fragments hoisted to registers ONCE (qf[8][2][4] = 64 regs), removing
// 16 ldsm/warp-iter and the S-phase dependency head.
#define QSTRIDE 272
#define VSTRIDE 528
#define PSTRIDE 144
#define KTILEB  (64 * QSTRIDE)            // 17408
#define VTILEB  (64 * VSTRIDE)            // 33792
#define SK_OFF  (128 * QSTRIDE)           // 34816 (after Q)
#define SV_OFF  (SK_OFF + 2 * KTILEB)     // 69632
#define SP_OFF  (SV_OFF + 2 * VTILEB)     // 137216
#define SDEN_OFF (SP_OFF + 128 * PSTRIDE) // 155648
#define FLASH_SMEM (SDEN_OFF + 512)       // 156160
#define NITER   (NTOK / 64)               // 64

__device__ __forceinline__ void kv_prefetch(uint32_t kb, uint32_t vb,
                                            const char* Kb, const char* Vb,
                                            int j0, int t) {
    #pragma unroll
    for (int i = 0; i < 4; i++) {          // K fp8: 64 rows x 256B
        int s = t + i * 256;
        int r = s >> 4, c = s & 15;
        CP_ASYNC16(kb + r * QSTRIDE + c * 16, Kb + (size_t)(j0 + r) * 256 + c * 16);
    }
    #pragma unroll
    for (int i = 0; i < 8; i++) {          // V bf16: 64 rows x 512B
        int s = t + i * 256;
        int r = s >> 5, c = s & 31;
        CP_ASYNC16(vb + r * VSTRIDE + c * 16, Vb + (size_t)(j0 + r) * 512 + c * 16);
    }
}

__global__ void __launch_bounds__(256, 1) flash_mix() {
    extern __shared__ char sm[];
    uint32_t smb = smem_to_u32(sm);
    float* sDenf = (float*)(sm + SDEN_OFF);
    const uint32_t sQ  = smb;
    const uint32_t sK0 = smb + SK_OFF;
    const uint32_t sV0 = smb + SV_OFF;
    const uint32_t sP  = smb + SP_OFF;

    int t = threadIdx.x, w = t >> 5, lane = t & 31;
    int grp = w & 3, dhalf = w >> 2;
    int i0 = blockIdx.x * 128, b = blockIdx.y;
    int gid = lane >> 2, qc = (lane & 3) * 2;

    const char* Qb = (const char*)(g_q8 + (size_t)b * NTOK * CCH);
    const char* Kb = (const char*)(g_k8 + (size_t)b * NTOK * CCH);
    const char* Vb = (const char*)(g_v  + (size_t)b * NTOK * CCH);

    // stage Q tile (128 x 256B fp8) + KV tile 0
    #pragma unroll
    for (int i = 0; i < 8; i++) {
        int s = t + i * 256;
        int r = s >> 4, c = s & 15;
        CP_ASYNC16(sQ + r * QSTRIDE + c * 16, Qb + (size_t)(i0 + r) * 256 + c * 16);
    }
    kv_prefetch(sK0, sV0, Kb, Vb, 0, t);
    CP_COMMIT();

    if (t < 128) sDenf[t] = 0.f;

    // per-lane ldsm bases
    uint32_t qbase = sQ + (grp * 32 + (lane & 15)) * QSTRIDE + ((lane >> 4) & 1) * 16;
    uint32_t kofs  = ((lane & 7) + ((lane >> 4) & 1) * 8) * QSTRIDE +
                     ((lane >> 3) & 1) * 16;
    uint32_t pldo  = sP + (grp * 32 + (lane & 15)) * PSTRIDE + ((lane >> 4) & 1) * 16;
    uint32_t vofs  = (lane & 15) * VSTRIDE + ((lane >> 4) & 1) * 16 + dhalf * 256;
    uint32_t pst   = sP + (grp * 32 + gid) * PSTRIDE + dhalf * 64 + qc * 2;

    // ---- wait for Q + tile 0, hoist Q fragments into registers ----
    CP_WAIT(0);
    __syncthreads();
    uint32_t qf[8][2][4];
    #pragma unroll
    for (int d = 0; d < 8; d++) {
        ldsm_x4(qbase + d * 32, qf[d][0]);
        ldsm_x4(qbase + 16 * QSTRIDE + d * 32, qf[d][1]);
    }

    float oacc[2][16][4];
    #pragma unroll
    for (int m = 0; m < 2; m++)
        #pragma unroll
        for (int n = 0; n < 16; n++)
            #pragma unroll
            for (int e = 0; e < 4; e++) oacc[m][n][e] = 0.f;
    float den[4] = {0.f, 0.f, 0.f, 0.f};

    #pragma unroll 1
    for (int it = 0; it < NITER; it++) {
        uint32_t kbuf = sK0 + (it & 1) * KTILEB;
        uint32_t vbuf = sV0 + (it & 1) * VTILEB;

        CP_WAIT(0);        // K(it), V(it) landed
        __syncthreads();   // publish; all warps finished iter it-1
        if (it + 1 < NITER) {
            kv_prefetch(sK0 + ((it + 1) & 1) * KTILEB,
                        sV0 + ((it + 1) & 1) * VTILEB, Kb, Vb, (it + 1) * 64, t);
            CP_COMMIT();
        }

        // ---- S(it) = Q' K^T (fp8): 32 rows x 32 tokens (dhalf) ----
        float sacc[2][4][4];
        #pragma unroll
        for (int m = 0; m < 2; m++)
            #pragma unroll
            for (int n = 0; n < 4; n++)
                #pragma unroll
                for (int e = 0; e < 4; e++) sacc[m][n][e] = 0.f;

        #pragma unroll
        for (int d = 0; d < 8; d++) {
            #pragma unroll
            for (int pp = 0; pp < 2; pp++) {
                uint32_t kb4[4];
                ldsm_x4(kbuf + kofs + (dhalf * 2 + pp) * (16 * QSTRIDE) + d * 32, kb4);
                mma16832(sacc[0][2 * pp],     qf[d][0], kb4[0], kb4[1]);
                mma16832(sacc[0][2 * pp + 1], qf[d][0], kb4[2], kb4[3]);
                mma16832(sacc[1][2 * pp],     qf[d][1], kb4[0], kb4[1]);
                mma16832(sacc[1][2 * pp + 1], qf[d][1], kb4[2], kb4[3]);
            }
        }

        // ---- P(it) = 2^S -> bf16 -> smem; denominator ----
        #pragma unroll
        for (int mt = 0; mt < 2; mt++) {
            #pragma unroll
            for (int nt = 0; nt < 4; nt++) {
                float e0 = ex2f(sacc[mt][nt][0]);
                float e1 = ex2f(sacc[mt][nt][1]);
                float e2 = ex2f(sacc[mt][nt][2]);
                float e3 = ex2f(sacc[mt][nt][3]);
                den[mt * 2 + 0] += e0 + e1;
                den[mt * 2 + 1] += e2 + e3;
                sts32(pst + (mt * 16) * PSTRIDE + nt * 16,     packbf2(e0, e1));
                sts32(pst + (mt * 16 + 8) * PSTRIDE + nt * 16, packbf2(e2, e3));
            }
        }
        // pair barrier: warps (grp) and (grp+4) both wrote their token halves
        asm volatile("bar.sync %0, 64;" :: "r"(1 + grp) : "memory");

        // ---- PV(it): O += P V, 32 rows x 128 ch, V frags shared over mt ----
        #pragma unroll
        for (int kc = 0; kc < 4; kc++) {
            uint32_t pa0[4], pa1[4];
            ldsm_x4(pldo + kc * 32, pa0);
            ldsm_x4(pldo + 16 * PSTRIDE + kc * 32, pa1);
            #pragma unroll
            for (int np = 0; np < 8; np++) {
                uint32_t vb4[4];
                ldsm_x4t(vbuf + vofs + kc * (16 * VSTRIDE) + np * 32, vb4);
                mma16816(oacc[0][2 * np],     pa0, vb4[0], vb4[1]);
                mma16816(oacc[0][2 * np + 1], pa0, vb4[2], vb4[3]);
                mma16816(oacc[1][2 * np],     pa1, vb4[0], vb4[1]);
                mma16816(oacc[1][2 * np + 1], pa1, vb4[2], vb4[3]);
            }
        }
    }

    // ---- combine denominators (quad-reduce, then across dhalf pair) ----
    #pragma unroll
    for (int i = 0; i < 4; i++) {
        den[i] += __shfl_xor_sync(~0u, den[i], 1);
        den[i] += __shfl_xor_sync(~0u, den[i], 2);
    }
    __syncthreads();
    if ((lane & 3) == 0) {
        atomicAdd(&sDenf[grp * 32 + gid],      den[0]);
        atomicAdd(&sDenf[grp * 32 + gid + 8],  den[1]);
        atomicAdd(&sDenf[grp * 32 + 16 + gid], den[2]);
        atomicAdd(&sDenf[grp * 32 + 24 + gid], den[3]);
    }
    __syncthreads();

    // ---- normalize + write ----
    bf16* Ap = g_a + ((size_t)b * NTOK + i0 + grp * 32) * CCH + dhalf * 128;
    #pragma unroll
    for (int mt = 0; mt < 2; mt++) {
        float invA = 1.f / sDenf[grp * 32 + mt * 16 + gid];
        float invB = 1.f / sDenf[grp * 32 + mt * 16 + gid + 8];
        #pragma unroll
        for (int nt = 0; nt < 16; nt++) {
            uint32_t lo = packbf2(oacc[mt][nt][0] * invA, oacc[mt][nt][1] * invA);
            uint32_t hi = packbf2(oacc[mt][nt][2] * invB, oacc[mt][nt][3] * invB);
            *(uint32_t*)(Ap + (size_t)(mt * 16 + gid) * CCH + nt * 8 + qc)     = lo;
            *(uint32_t*)(Ap + (size_t)(mt * 16 + gid + 8) * CCH + nt * 8 + qc) = hi;
        }
    }
}

// -------- 5) proj GEMM + residual (cp.async + bf16 weights) --------
__global__ void __launch_bounds__(256) proj_gemm(const float* __restrict__ bias,
                                                 const float* __restrict__ x,
                                                 float* __restrict__ out) {
    extern __shared__ char sm[];
    uint32_t smb = smem_to_u32(sm);
    float* sOut = (float*)sm;

    int m0 = blockIdx.x * 128;
    int d0 = blockIdx.y * 128;
    int b  = blockIdx.z;
    const char* Ab = (const char*)(g_a + (size_t)b * NTOK * CCH);
    const char* Bb = (const char*)(g_wb[3]);

    int t = threadIdx.x;
    int wid = t >> 5;
    int wm = wid & 3, wn = wid >> 2;

    wmma::fragment<wmma::accumulator, 16, 16, 16, float> acc[2][4];
    #pragma unroll
    for (int i = 0; i < 2; i++)
        #pragma unroll
        for (int j = 0; j < 4; j++) wmma::fill_fragment(acc[i][j], 0.f);

    gemm_tile_load(smb, smb + GT, Ab, Bb, m0, d0, 0, t);
    CP_COMMIT();

    for (int ch = 0; ch < 4; ch++) {
        if (ch + 1 < 4) {
            gemm_tile_load(smb + ((ch + 1) & 1) * 2 * GT,
                           smb + ((ch + 1) & 1) * 2 * GT + GT, Ab, Bb, m0, d0, ch + 1, t);
            CP_COMMIT();
            CP_WAIT(1);
        } else {
            CP_WAIT(0);
        }
        __syncthreads();
        bf16* sA = (bf16*)(sm + (ch & 1) * 2 * GT);
        bf16* sB = (bf16*)(sm + (ch & 1) * 2 * GT + GT);
        #pragma unroll
        for (int ks = 0; ks < 4; ks++) {
            wmma::fragment<wmma::matrix_a, 16, 16, 16, bf16, wmma::row_major> af0, af1;
            wmma::load_matrix_sync(af0, &sA[(wm * 32) * 72 + ks * 16], 72);
            wmma::load_matrix_sync(af1, &sA[(wm * 32 + 16) * 72 + ks * 16], 72);
            #pragma unroll
            for (int ni = 0; ni < 4; ni++) {
                wmma::fragment<wmma::matrix_b, 16, 16, 16, bf16, wmma::col_major> bfr;
                wmma::load_matrix_sync(bfr, &sB[ks * 16 + (wn * 64 + ni * 16) * 72], 72);
                wmma::mma_sync(acc[0][ni], af0, bfr, acc[0][ni]);
                wmma::mma_sync(acc[1][ni], af1, bfr, acc[1][ni]);
            }
        }
        __syncthreads();
    }
    #pragma unroll
    for (int i = 0; i < 2; i++)
        #pragma unroll
        for (int j = 0; j < 4; j++)
            wmma::store_matrix_sync(&sOut[(wm * 32 + i * 16) * 136 + wn * 64 + j * 16],
                                    acc[i][j], 136, wmma::mem_row_major);
    __syncthreads();
    for (int idx = t; idx < 128 * 128; idx += 256) {
        int dd = idx >> 7, r = idx & 127;
        size_t o = ((size_t)(b * CCH + d0 + dd)) * NTOK + m0 + r;
        out[o] = sOut[r * 136 + dd] + bias[d0 + dd] + x[o];
    }
}

// ------------------------------- launch ------------------------------------
extern "C" void kernel_launch(void* const* d_in, const int* in_sizes, int n_in,
                              void* d_out, int out_size) {
    const float* x  = (const float*)d_in[0];
    const float* gs = (const float*)d_in[1];
    const float* gb = (const float*)d_in[2];
    const float* wq = (const float*)d_in[3];
    const float* bq = (const float*)d_in[4];
    const float* wk = (const float*)d_in[5];
    const float* bk = (const float*)d_in[6];
    const float* wv = (const float*)d_in[7];
    const float* bv = (const float*)d_in[8];
    const float* wp = (const float*)d_in[9];
    const float* bp = (const float*)d_in[10];
    float* out = (float*)d_out;

    cudaFuncSetAttribute(qkv_gemm,  cudaFuncAttributeMaxDynamicSharedMemorySize, QKV_SMEM);
    cudaFuncSetAttribute(proj_gemm, cudaFuncAttributeMaxDynamicSharedMemorySize, QKV_SMEM);
    cudaFuncSetAttribute(flash_mix, cudaFuncAttributeMaxDynamicSharedMemorySize, FLASH_SMEM);

    w_cvt<<<64, 256>>>(wq, wk, wv, wp);
    gn_stats<<<BATCH * GRP, 256>>>(x);
    gn_apply<<<dim3(NTOK / 32, CCH / 32, BATCH), dim3(32, 8)>>>(x, gs, gb);

    qkv_gemm<<<dim3(NTOK / 128, CCH / 128, BATCH * 3), 256, QKV_SMEM>>>(bq, bk, bv);

    flash_mix<<<dim3(NTOK / 128, BATCH), 256, FLASH_SMEM>>>();

    proj_gemm<<<dim3(NTOK / 128, CCH / 128, BATCH), 256, QKV_SMEM>>>(bp, x, out);
}

// round 14
// speedup vs baseline: 1.1089x; 1.1089x over previous
#include <cuda_runtime.h>
#include <cuda_bf16.h>
#include <mma.h>
#include <cstdint>

using namespace nvcuda;
typedef __nv_bfloat16 bf16;

#define BATCH 4
#define CCH   256
#define GRP   32
#define NTOK  4096
#define EPS   1e-6f
// exp(q.k/16) = 2^(q'.k) with q' = q * log2(e)/16
#define QSCALE 0.09016843785f

// ---------------------------- PTX helpers -----------------------------------
__device__ __forceinline__ uint32_t smem_to_u32(const void* p) {
    uint32_t a;
    asm("{ .reg .u64 tmp; cvta.to.shared.u64 tmp, %1; cvt.u32.u64 %0, tmp; }"
        : "=r"(a) : "l"(p));
    return a;
}
#define CP_ASYNC16(dst, src) \
    asm volatile("cp.async.cg.shared.global [%0], [%1], 16;" :: "r"(dst), "l"(src))
#define CP_COMMIT() asm volatile("cp.async.commit_group;" ::: "memory")
#define CP_WAIT(n)  asm volatile("cp.async.wait_group %0;" :: "n"(n) : "memory")

__device__ __forceinline__ void ldsm_x4(uint32_t addr, uint32_t r[4]) {
    asm volatile("ldmatrix.sync.aligned.m8n8.x4.shared.b16 {%0,%1,%2,%3}, [%4];"
                 : "=r"(r[0]), "=r"(r[1]), "=r"(r[2]), "=r"(r[3]) : "r"(addr));
}
__device__ __forceinline__ void ldsm_x4t(uint32_t addr, uint32_t r[4]) {
    asm volatile("ldmatrix.sync.aligned.m8n8.x4.trans.shared.b16 {%0,%1,%2,%3}, [%4];"
                 : "=r"(r[0]), "=r"(r[1]), "=r"(r[2]), "=r"(r[3]) : "r"(addr));
}
// bf16 MMA: D(f32) += A(bf16 m16k16) * B(bf16 k16n8)
__device__ __forceinline__ void mma16816(float c[4], const uint32_t a[4],
                                         uint32_t b0, uint32_t b1) {
    asm volatile("mma.sync.aligned.m16n8k16.row.col.f32.bf16.bf16.f32 "
                 "{%0,%1,%2,%3}, {%4,%5,%6,%7}, {%8,%9}, {%0,%1,%2,%3};"
                 : "+f"(c[0]), "+f"(c[1]), "+f"(c[2]), "+f"(c[3])
                 : "r"(a[0]), "r"(a[1]), "r"(a[2]), "r"(a[3]), "r"(b0), "r"(b1));
}
// fp8 e4m3 MMA: D(f32) += A(e4m3 m16k32) * B(e4m3 k32n8)
__device__ __forceinline__ void mma16832(float c[4], const uint32_t a[4],
                                         uint32_t b0, uint32_t b1) {
    asm volatile("mma.sync.aligned.m16n8k32.row.col.f32.e4m3.e4m3.f32 "
                 "{%0,%1,%2,%3}, {%4,%5,%6,%7}, {%8,%9}, {%0,%1,%2,%3};"
                 : "+f"(c[0]), "+f"(c[1]), "+f"(c[2]), "+f"(c[3])
                 : "r"(a[0]), "r"(a[1]), "r"(a[2]), "r"(a[3]), "r"(b0), "r"(b1));
}
__device__ __forceinline__ float ex2f(float x) {
    float y;
    asm("ex2.approx.f32 %0, %1;" : "=f"(y) : "f"(x));
    return y;
}
__device__ __forceinline__ uint32_t packbf2(float a, float b) {
    __nv_bfloat162 h = __floats2bfloat162_rn(a, b);
    return *(uint32_t*)&h;
}
__device__ __forceinline__ uint32_t pack_e4m3(float lo, float hi) {
    uint16_t r;
    asm("cvt.rn.satfinite.e4m3x2.f32 %0, %1, %2;" : "=h"(r) : "f"(hi), "f"(lo));
    return (uint32_t)r;
}
__device__ __forceinline__ void sts32(uint32_t addr, uint32_t v) {
    asm volatile("st.shared.b32 [%0], %1;" :: "r"(addr), "r"(v));
}

// ---------------- scratch (device globals; no allocs allowed) ----------------
__device__ float   g_mean[BATCH * GRP];
__device__ float   g_rstd[BATCH * GRP];
__device__ bf16    g_hn[BATCH * NTOK * CCH];   // [b][n][c]
__device__ bf16    g_wb[4][CCH * CCH];         // wq,wk,wv,wp in bf16
__device__ uint8_t g_q8[BATCH * NTOK * CCH];   // [b][n][c]  e4m3, pre-scaled
__device__ uint8_t g_k8[BATCH * NTOK * CCH];   // [b][n][c]  e4m3
__device__ bf16    g_v [BATCH * NTOK * CCH];   // [b][n][c]  bf16
__device__ bf16    g_a [BATCH * NTOK * CCH];   // attention output (normalized)

// ---------------- 0) weight conversion fp32 -> bf16 ----------------
__global__ void w_cvt(const float* __restrict__ wq, const float* __restrict__ wk,
                      const float* __restrict__ wv, const float* __restrict__ wp) {
    int i = blockIdx.x * blockDim.x + threadIdx.x;   // 0..16383 (float4 index)
    const float* srcs[4] = {wq, wk, wv, wp};
    #pragma unroll
    for (int m = 0; m < 4; m++) {
        float4 f = ((const float4*)srcs[m])[i];
        __nv_bfloat162* d = (__nv_bfloat162*)&g_wb[m][i * 4];
        d[0] = __float22bfloat162_rn(make_float2(f.x, f.y));
        d[1] = __float22bfloat162_rn(make_float2(f.z, f.w));
    }
}

// ---------------- 1) GroupNorm statistics ----------------
__global__ void gn_stats(const float* __restrict__ x) {
    int bg = blockIdx.x;
    const float4* p = (const float4*)(x + (size_t)bg * (8 * NTOK));
    float s = 0.f, sq = 0.f;
    for (int i = threadIdx.x; i < (8 * NTOK) / 4; i += blockDim.x) {
        float4 v = p[i];
        s  += v.x + v.y + v.z + v.w;
        sq += v.x * v.x + v.y * v.y + v.z * v.z + v.w * v.w;
    }
    __shared__ float ss[32], ssq[32];
    #pragma unroll
    for (int o = 16; o; o >>= 1) {
        s  += __shfl_xor_sync(~0u, s, o);
        sq += __shfl_xor_sync(~0u, sq, o);
    }
    int w = threadIdx.x >> 5, l = threadIdx.x & 31;
    if (l == 0) { ss[w] = s; ssq[w] = sq; }
    __syncthreads();
    if (w == 0) {
        s  = (l < (int)(blockDim.x >> 5)) ? ss[l]  : 0.f;
        sq = (l < (int)(blockDim.x >> 5)) ? ssq[l] : 0.f;
        #pragma unroll
        for (int o = 16; o; o >>= 1) {
            s  += __shfl_xor_sync(~0u, s, o);
            sq += __shfl_xor_sync(~0u, sq, o);
        }
        if (l == 0) {
            float m   = s / (8.f * NTOK);
            float var = sq / (8.f * NTOK) - m * m;
            g_mean[bg] = m;
            g_rstd[bg] = rsqrtf(var + EPS);
        }
    }
}

// ------- 2) GroupNorm apply + transpose to bf16 [b][n][c] -------
__global__ void gn_apply(const float* __restrict__ x,
                         const float* __restrict__ gs,
                         const float* __restrict__ gb) {
    __shared__ float tile[32][33];
    int n0 = blockIdx.x * 32, c0 = blockIdx.y * 32, b = blockIdx.z;
    int tx = threadIdx.x, ty = threadIdx.y;
    #pragma unroll
    for (int j = 0; j < 4; j++) {
        int c = c0 + ty + j * 8;
        float v = x[((size_t)(b * CCH + c)) * NTOK + n0 + tx];
        int gi = b * GRP + (c >> 3);
        v = (v - g_mean[gi]) * g_rstd[gi] * gs[c] + gb[c];
        tile[ty + j * 8][tx] = v;
    }
    __syncthreads();
    #pragma unroll
    for (int j = 0; j < 4; j++) {
        int n = n0 + ty + j * 8;
        g_hn[((size_t)(b * NTOK + n)) * CCH + c0 + tx] =
            __float2bfloat16(tile[tx][ty + j * 8]);
    }
}

// -------- 3) fused QKV GEMM, cp.async + bf16 weights. z=(b,sel). -------------
#define GT 18432                          // one tile: 128 x 144 B
#define QKV_SMEM (4 * GT)                 // 73728 (>= epilogue 69632)

__device__ __forceinline__ void gemm_tile_load(uint32_t sA, uint32_t sB,
                                               const char* Ab, const char* Bb,
                                               int m0, int d0, int ch, int t) {
    #pragma unroll
    for (int i = 0; i < 4; i++) {
        int s = t + i * 256;
        int r = s >> 3, c = s & 7;
        CP_ASYNC16(sA + r * 144 + c * 16, Ab + (size_t)(m0 + r) * 512 + ch * 128 + c * 16);
    }
    #pragma unroll
    for (int i = 0; i < 4; i++) {
        int s = t + i * 256;
        int r = s >> 3, c = s & 7;
        CP_ASYNC16(sB + r * 144 + c * 16, Bb + (size_t)(d0 + r) * 512 + ch * 128 + c * 16);
    }
}

__global__ void __launch_bounds__(256) qkv_gemm(
        const float* __restrict__ bq, const float* __restrict__ bk,
        const float* __restrict__ bv) {
    extern __shared__ char sm[];
    uint32_t smb = smem_to_u32(sm);
    float* sOut = (float*)sm;

    int m0  = blockIdx.x * 128;
    int d0  = blockIdx.y * 128;
    int b   = blockIdx.z / 3;
    int sel = blockIdx.z % 3;
    const float* bias = (sel == 0) ? bq : (sel == 1) ? bk : bv;
    const char* Ab = (const char*)(g_hn + (size_t)b * NTOK * CCH);
    const char* Bb = (const char*)(g_wb[sel]);

    int t = threadIdx.x;
    int wid = t >> 5;
    int wm = wid & 3, wn = wid >> 2;

    wmma::fragment<wmma::accumulator, 16, 16, 16, float> acc[2][4];
    #pragma unroll
    for (int i = 0; i < 2; i++)
        #pragma unroll
        for (int j = 0; j < 4; j++) wmma::fill_fragment(acc[i][j], 0.f);

    gemm_tile_load(smb, smb + GT, Ab, Bb, m0, d0, 0, t);
    CP_COMMIT();

    for (int ch = 0; ch < 4; ch++) {
        if (ch + 1 < 4) {
            gemm_tile_load(smb + ((ch + 1) & 1) * 2 * GT,
                           smb + ((ch + 1) & 1) * 2 * GT + GT, Ab, Bb, m0, d0, ch + 1, t);
            CP_COMMIT();
            CP_WAIT(1);
        } else {
            CP_WAIT(0);
        }
        __syncthreads();
        bf16* sA = (bf16*)(sm + (ch & 1) * 2 * GT);
        bf16* sB = (bf16*)(sm + (ch & 1) * 2 * GT + GT);
        #pragma unroll
        for (int ks = 0; ks < 4; ks++) {
            wmma::fragment<wmma::matrix_a, 16, 16, 16, bf16, wmma::row_major> af0, af1;
            wmma::load_matrix_sync(af0, &sA[(wm * 32) * 72 + ks * 16], 72);
            wmma::load_matrix_sync(af1, &sA[(wm * 32 + 16) * 72 + ks * 16], 72);
            #pragma unroll
            for (int ni = 0; ni < 4; ni++) {
                wmma::fragment<wmma::matrix_b, 16, 16, 16, bf16, wmma::col_major> bfr;
                wmma::load_matrix_sync(bfr, &sB[ks * 16 + (wn * 64 + ni * 16) * 72], 72);
                wmma::mma_sync(acc[0][ni], af0, bfr, acc[0][ni]);
                wmma::mma_sync(acc[1][ni], af1, bfr, acc[1][ni]);
            }
        }
        __syncthreads();
    }
    #pragma unroll
    for (int i = 0; i < 2; i++)
        #pragma unroll
        for (int j = 0; j < 4; j++)
            wmma::store_matrix_sync(&sOut[(wm * 32 + i * 16) * 136 + wn * 64 + j * 16],
                                    acc[i][j], 136, wmma::mem_row_major);
    __syncthreads();
    if (sel == 2) {
        for (int idx = t; idx < 128 * 128; idx += 256) {
            int r = idx >> 7, cc = idx & 127;
            float v = sOut[r * 136 + cc] + bias[d0 + cc];
            g_v[(size_t)(b * NTOK + m0 + r) * CCH + d0 + cc] = __float2bfloat16(v);
        }
    } else {
        uint8_t* out = (sel == 0) ? g_q8 : g_k8;
        float oscale = (sel == 0) ? QSCALE : 1.0f;
        for (int idx = t; idx < 128 * 64; idx += 256) {
            int r = idx >> 6, cc = idx & 63;
            float v0 = (sOut[r * 136 + 2 * cc]     + bias[d0 + 2 * cc])     * oscale;
            float v1 = (sOut[r * 136 + 2 * cc + 1] + bias[d0 + 2 * cc + 1]) * oscale;
            uint16_t pk = (uint16_t)pack_e4m3(v0, v1);
            *(uint16_t*)(out + (size_t)(b * NTOK + m0 + r) * CCH + d0 + 2 * cc) = pk;
        }
    }
}

// ------------------- 4) Flash attention: PV_own from registers --------------
// BM=128 rows/CTA, 8 warps: grp=w&3 owns rows grp*32..+32, dhalf=w>>2 owns
// channels dhalf*128..+128 and tokens dhalf*32..+32 for S. BN=64.
// Per iter: S(own 32 tok) -> exp: pack pa_own (regs) + sts P (for partner)
//   -> PV_own (NO barrier, regs) -> pair bar -> PV_partner (P via ldsm).
#define QSTRIDE 272
#define VSTRIDE 528
#define PSTRIDE 144
#define KTILEB  (64 * QSTRIDE)            // 17408
#define VTILEB  (64 * VSTRIDE)            // 33792
#define SK_OFF  (128 * QSTRIDE)           // 34816 (after Q)
#define SV_OFF  (SK_OFF + 2 * KTILEB)     // 69632
#define SP_OFF  (SV_OFF + 2 * VTILEB)     // 137216
#define SDEN_OFF (SP_OFF + 128 * PSTRIDE) // 155648
#define FLASH_SMEM (SDEN_OFF + 512)       // 156160
#define NITER   (NTOK / 64)               // 64

__device__ __forceinline__ void kv_prefetch(uint32_t kb, uint32_t vb,
                                            const char* Kb, const char* Vb,
                                            int j0, int t) {
    #pragma unroll
    for (int i = 0; i < 4; i++) {          // K fp8: 64 rows x 256B
        int s = t + i * 256;
        int r = s >> 4, c = s & 15;
        CP_ASYNC16(kb + r * QSTRIDE + c * 16, Kb + (size_t)(j0 + r) * 256 + c * 16);
    }
    #pragma unroll
    for (int i = 0; i < 8; i++) {          // V bf16: 64 rows x 512B
        int s = t + i * 256;
        int r = s >> 5, c = s & 31;
        CP_ASYNC16(vb + r * VSTRIDE + c * 16, Vb + (size_t)(j0 + r) * 512 + c * 16);
    }
}

__global__ void __launch_bounds__(256, 1) flash_mix() {
    extern __shared__ char sm[];
    uint32_t smb = smem_to_u32(sm);
    float* sDenf = (float*)(sm + SDEN_OFF);
    const uint32_t sQ  = smb;
    const uint32_t sK0 = smb + SK_OFF;
    const uint32_t sV0 = smb + SV_OFF;
    const uint32_t sP  = smb + SP_OFF;

    int t = threadIdx.x, w = t >> 5, lane = t & 31;
    int grp = w & 3, dhalf = w >> 2;
    int i0 = blockIdx.x * 128, b = blockIdx.y;
    int gid = lane >> 2, qc = (lane & 3) * 2;

    const char* Qb = (const char*)(g_q8 + (size_t)b * NTOK * CCH);
    const char* Kb = (const char*)(g_k8 + (size_t)b * NTOK * CCH);
    const char* Vb = (const char*)(g_v  + (size_t)b * NTOK * CCH);

    // stage Q tile (128 x 256B fp8) + KV tile 0
    #pragma unroll
    for (int i = 0; i < 8; i++) {
        int s = t + i * 256;
        int r = s >> 4, c = s & 15;
        CP_ASYNC16(sQ + r * QSTRIDE + c * 16, Qb + (size_t)(i0 + r) * 256 + c * 16);
    }
    kv_prefetch(sK0, sV0, Kb, Vb, 0, t);
    CP_COMMIT();

    if (t < 128) sDenf[t] = 0.f;

    // per-lane ldsm bases
    uint32_t qbase = sQ + (grp * 32 + (lane & 15)) * QSTRIDE + ((lane >> 4) & 1) * 16;
    uint32_t kofs  = ((lane & 7) + ((lane >> 4) & 1) * 8) * QSTRIDE +
                     ((lane >> 3) & 1) * 16;
    uint32_t pldo  = sP + (grp * 32 + (lane & 15)) * PSTRIDE + ((lane >> 4) & 1) * 16;
    uint32_t vofs  = (lane & 15) * VSTRIDE + ((lane >> 4) & 1) * 16 + dhalf * 256;
    uint32_t pst   = sP + (grp * 32 + gid) * PSTRIDE + dhalf * 64 + qc * 2;

    float oacc[2][16][4];
    #pragma unroll
    for (int m = 0; m < 2; m++)
        #pragma unroll
        for (int n = 0; n < 16; n++)
            #pragma unroll
            for (int e = 0; e < 4; e++) oacc[m][n][e] = 0.f;
    float den[4] = {0.f, 0.f, 0.f, 0.f};

    #pragma unroll 1
    for (int it = 0; it < NITER; it++) {
        uint32_t kbuf = sK0 + (it & 1) * KTILEB;
        uint32_t vbuf = sV0 + (it & 1) * VTILEB;

        CP_WAIT(0);        // K(it), V(it) landed
        __syncthreads();   // publish; all warps finished iter it-1
        if (it + 1 < NITER) {
            kv_prefetch(sK0 + ((it + 1) & 1) * KTILEB,
                        sV0 + ((it + 1) & 1) * VTILEB, Kb, Vb, (it + 1) * 64, t);
            CP_COMMIT();
        }

        // ---- S(it) = Q' K^T (fp8): 32 rows x 32 own tokens ----
        float sacc[2][4][4];
        #pragma unroll
        for (int m = 0; m < 2; m++)
            #pragma unroll
            for (int n = 0; n < 4; n++)
                #pragma unroll
                for (int e = 0; e < 4; e++) sacc[m][n][e] = 0.f;

        #pragma unroll
        for (int d = 0; d < 8; d++) {
            uint32_t qa0[4], qa1[4];
            ldsm_x4(qbase + d * 32, qa0);
            ldsm_x4(qbase + 16 * QSTRIDE + d * 32, qa1);
            #pragma unroll
            for (int pp = 0; pp < 2; pp++) {
                uint32_t kb4[4];
                ldsm_x4(kbuf + kofs + (dhalf * 2 + pp) * (16 * QSTRIDE) + d * 32, kb4);
                mma16832(sacc[0][2 * pp],     qa0, kb4[0], kb4[1]);
                mma16832(sacc[0][2 * pp + 1], qa0, kb4[2], kb4[3]);
                mma16832(sacc[1][2 * pp],     qa1, kb4[0], kb4[1]);
                mma16832(sacc[1][2 * pp + 1], qa1, kb4[2], kb4[3]);
            }
        }

        // ---- P(it) = 2^S: pack pa_own (regs) + sts P (partner); denom ----
        uint32_t pown[2][2][4];   // [mt][kcl][frag]
        #pragma unroll
        for (int mt = 0; mt < 2; mt++) {
            #pragma unroll
            for (int nt = 0; nt < 4; nt++) {
                float e0 = ex2f(sacc[mt][nt][0]);
                float e1 = ex2f(sacc[mt][nt][1]);
                float e2 = ex2f(sacc[mt][nt][2]);
                float e3 = ex2f(sacc[mt][nt][3]);
                den[mt * 2 + 0] += e0 + e1;
                den[mt * 2 + 1] += e2 + e3;
                uint32_t lo = packbf2(e0, e1);
                uint32_t hi = packbf2(e2, e3);
                pown[mt][nt >> 1][(nt & 1) * 2 + 0] = lo;
                pown[mt][nt >> 1][(nt & 1) * 2 + 1] = hi;
                sts32(pst + (mt * 16) * PSTRIDE + nt * 16,     lo);
                sts32(pst + (mt * 16 + 8) * PSTRIDE + nt * 16, hi);
            }
        }

        // ---- PV_own: O += P_own V[own tokens, own channels] (no barrier) ----
        #pragma unroll
        for (int kcl = 0; kcl < 2; kcl++) {
            int kc = dhalf * 2 + kcl;
            #pragma unroll
            for (int np = 0; np < 8; np++) {
                uint32_t vb4[4];
                ldsm_x4t(vbuf + vofs + kc * (16 * VSTRIDE) + np * 32, vb4);
                mma16816(oacc[0][2 * np],     pown[0][kcl], vb4[0], vb4[1]);
                mma16816(oacc[0][2 * np + 1], pown[0][kcl], vb4[2], vb4[3]);
                mma16816(oacc[1][2 * np],     pown[1][kcl], vb4[0], vb4[1]);
                mma16816(oacc[1][2 * np + 1], pown[1][kcl], vb4[2], vb4[3]);
            }
        }

        // pair barrier: partner finished its P stores (it stores before PV_own)
        asm volatile("bar.sync %0, 64;" :: "r"(1 + grp) : "memory");

        // ---- PV_partner: O += P_partner V[partner tokens, own channels] ----
        #pragma unroll
        for (int kcl = 0; kcl < 2; kcl++) {
            int kc = (1 - dhalf) * 2 + kcl;
            uint32_t pa0[4], pa1[4];
            ldsm_x4(pldo + kc * 32, pa0);
            ldsm_x4(pldo + 16 * PSTRIDE + kc * 32, pa1);
            #pragma unroll
            for (int np = 0; np < 8; np++) {
                uint32_t vb4[4];
                ldsm_x4t(vbuf + vofs + kc * (16 * VSTRIDE) + np * 32, vb4);
                mma16816(oacc[0][2 * np],     pa0, vb4[0], vb4[1]);
                mma16816(oacc[0][2 * np + 1], pa0, vb4[2], vb4[3]);
                mma16816(oacc[1][2 * np],     pa1, vb4[0], vb4[1]);
                mma16816(oacc[1][2 * np + 1], pa1, vb4[2], vb4[3]);
            }
        }
    }

    // ---- combine denominators (quad-reduce, then across dhalf pair) ----
    #pragma unroll
    for (int i = 0; i < 4; i++) {
        den[i] += __shfl_xor_sync(~0u, den[i], 1);
        den[i] += __shfl_xor_sync(~0u, den[i], 2);
    }
    __syncthreads();
    if ((lane & 3) == 0) {
        atomicAdd(&sDenf[grp * 32 + gid],      den[0]);
        atomicAdd(&sDenf[grp * 32 + gid + 8],  den[1]);
        atomicAdd(&sDenf[grp * 32 + 16 + gid], den[2]);
        atomicAdd(&sDenf[grp * 32 + 24 + gid], den[3]);
    }
    __syncthreads();

    // ---- normalize + write ----
    bf16* Ap = g_a + ((size_t)b * NTOK + i0 + grp * 32) * CCH + dhalf * 128;
    #pragma unroll
    for (int mt = 0; mt < 2; mt++) {
        float invA = 1.f / sDenf[grp * 32 + mt * 16 + gid];
        float invB = 1.f / sDenf[grp * 32 + mt * 16 + gid + 8];
        #pragma unroll
        for (int nt = 0; nt < 16; nt++) {
            uint32_t lo = packbf2(oacc[mt][nt][0] * invA, oacc[mt][nt][1] * invA);
            uint32_t hi = packbf2(oacc[mt][nt][2] * invB, oacc[mt][nt][3] * invB);
            *(uint32_t*)(Ap + (size_t)(mt * 16 + gid) * CCH + nt * 8 + qc)     = lo;
            *(uint32_t*)(Ap + (size_t)(mt * 16 + gid + 8) * CCH + nt * 8 + qc) = hi;
        }
    }
}

// -------- 5) proj GEMM + residual (cp.async + bf16 weights) --------
__global__ void __launch_bounds__(256) proj_gemm(const float* __restrict__ bias,
                                                 const float* __restrict__ x,
                                                 float* __restrict__ out) {
    extern __shared__ char sm[];
    uint32_t smb = smem_to_u32(sm);
    float* sOut = (float*)sm;

    int m0 = blockIdx.x * 128;
    int d0 = blockIdx.y * 128;
    int b  = blockIdx.z;
    const char* Ab = (const char*)(g_a + (size_t)b * NTOK * CCH);
    const char* Bb = (const char*)(g_wb[3]);

    int t = threadIdx.x;
    int wid = t >> 5;
    int wm = wid & 3, wn = wid >> 2;

    wmma::fragment<wmma::accumulator, 16, 16, 16, float> acc[2][4];
    #pragma unroll
    for (int i = 0; i < 2; i++)
        #pragma unroll
        for (int j = 0; j < 4; j++) wmma::fill_fragment(acc[i][j], 0.f);

    gemm_tile_load(smb, smb + GT, Ab, Bb, m0, d0, 0, t);
    CP_COMMIT();

    for (int ch = 0; ch < 4; ch++) {
        if (ch + 1 < 4) {
            gemm_tile_load(smb + ((ch + 1) & 1) * 2 * GT,
                           smb + ((ch + 1) & 1) * 2 * GT + GT, Ab, Bb, m0, d0, ch + 1, t);
            CP_COMMIT();
            CP_WAIT(1);
        } else {
            CP_WAIT(0);
        }
        __syncthreads();
        bf16* sA = (bf16*)(sm + (ch & 1) * 2 * GT);
        bf16* sB = (bf16*)(sm + (ch & 1) * 2 * GT + GT);
        #pragma unroll
        for (int ks = 0; ks < 4; ks++) {
            wmma::fragment<wmma::matrix_a, 16, 16, 16, bf16, wmma::row_major> af0, af1;
            wmma::load_matrix_sync(af0, &sA[(wm * 32) * 72 + ks * 16], 72);
            wmma::load_matrix_sync(af1, &sA[(wm * 32 + 16) * 72 + ks * 16], 72);
            #pragma unroll
            for (int ni = 0; ni < 4; ni++) {
                wmma::fragment<wmma::matrix_b, 16, 16, 16, bf16, wmma::col_major> bfr;
                wmma::load_matrix_sync(bfr, &sB[ks * 16 + (wn * 64 + ni * 16) * 72], 72);
                wmma::mma_sync(acc[0][ni], af0, bfr, acc[0][ni]);
                wmma::mma_sync(acc[1][ni], af1, bfr, acc[1][ni]);
            }
        }
        __syncthreads();
    }
    #pragma unroll
    for (int i = 0; i < 2; i++)
        #pragma unroll
        for (int j = 0; j < 4; j++)
            wmma::store_matrix_sync(&sOut[(wm * 32 + i * 16) * 136 + wn * 64 + j * 16],
                                    acc[i][j], 136, wmma::mem_row_major);
    __syncthreads();
    for (int idx = t; idx < 128 * 128; idx += 256) {
        int dd = idx >> 7, r = idx & 127;
        size_t o = ((size_t)(b * CCH + d0 + dd)) * NTOK + m0 + r;
        out[o] = sOut[r * 136 + dd] + bias[d0 + dd] + x[o];
    }
}

// ------------------------------- launch ------------------------------------
extern "C" void kernel_launch(void* const* d_in, const int* in_sizes, int n_in,
                              void* d_out, int out_size) {
    const float* x  = (const float*)d_in[0];
    const float* gs = (const float*)d_in[1];
    const float* gb = (const float*)d_in[2];
    const float* wq = (const float*)d_in[3];
    const float* bq = (const float*)d_in[4];
    const float* wk = (const float*)d_in[5];
    const float* bk = (const float*)d_in[6];
    const float* wv = (const float*)d_in[7];
    const float* bv = (const float*)d_in[8];
    const float* wp = (const float*)d_in[9];
    const float* bp = (const float*)d_in[10];
    float* out = (float*)d_out;

    cudaFuncSetAttribute(qkv_gemm,  cudaFuncAttributeMaxDynamicSharedMemorySize, QKV_SMEM);
    cudaFuncSetAttribute(proj_gemm, cudaFuncAttributeMaxDynamicSharedMemorySize, QKV_SMEM);
    cudaFuncSetAttribute(flash_mix, cudaFuncAttributeMaxDynamicSharedMemorySize, FLASH_SMEM);

    w_cvt<<<64, 256>>>(wq, wk, wv, wp);
    gn_stats<<<BATCH * GRP, 256>>>(x);
    gn_apply<<<dim3(NTOK / 32, CCH / 32, BATCH), dim3(32, 8)>>>(x, gs, gb);

    qkv_gemm<<<dim3(NTOK / 128, CCH / 128, BATCH * 3), 256, QKV_SMEM>>>(bq, bk, bv);

    flash_mix<<<dim3(NTOK / 128, BATCH), 256, FLASH_SMEM>>>();

    proj_gemm<<<dim3(NTOK / 128, CCH / 128, BATCH), 256, QKV_SMEM>>>(bp, x, out);
}